// round 10
// baseline (speedup 1.0000x reference)
#include <cuda_runtime.h>

// out[b, j] = prod_{i<=j} cos(params[i]) * cos(x[b, i])
// (RX/RY product state; CNOT chain => prefix-XOR => prefix product of <Z>.)
//
// Warp-segmented inclusive product scan, 2 triples (6 rows) per warp:
//  - both row-triple loads issued up front (MLP=2, one DRAM round trip)
//  - the two 4-step shfl scan chains are interleaved so their latencies overlap
//  - 171 blocks instead of 683 (less block-distribution overhead)

#define N_WIRES 10

__global__ void __launch_bounds__(512)
qgate_kernel(const float* __restrict__ x,
             const float* __restrict__ params,
             float* __restrict__ out,
             int B)
{
    int gtid = blockIdx.x * blockDim.x + threadIdx.x;
    int warp = gtid >> 5;
    int lane = threadIdx.x & 31;
    int seg  = lane / N_WIRES;            // 0..2 useful, 3 = idle lanes
    int col  = lane - seg * N_WIRES;

    int row0 = warp * 6 + seg;            // first triple
    int row1 = row0 + 3;                  // second triple

    bool a0 = (seg < 3) && (row0 < B);
    bool a1 = (seg < 3) && (row1 < B);

    // Front-batched loads: 2 outstanding LDGs, single exposed DRAM latency.
    float v0 = 1.0f, v1 = 1.0f;
    float pc = (seg < 3) ? __cosf(params[col]) : 1.0f;   // L1 broadcast
    if (a0) v0 = pc * __cosf(__ldg(&x[row0 * N_WIRES + col]));
    if (a1) v1 = pc * __cosf(__ldg(&x[row1 * N_WIRES + col]));

    // Interleaved segmented inclusive product scans (segments of N_WIRES).
#pragma unroll
    for (int d = 1; d < N_WIRES; d <<= 1) {
        float u0 = __shfl_up_sync(0xFFFFFFFFu, v0, d);
        float u1 = __shfl_up_sync(0xFFFFFFFFu, v1, d);
        if (col >= d) { v0 *= u0; v1 *= u1; }
    }

    if (a0) out[row0 * N_WIRES + col] = v0;
    if (a1) out[row1 * N_WIRES + col] = v1;
}

extern "C" void kernel_launch(void* const* d_in, const int* in_sizes, int n_in,
                              void* d_out, int out_size)
{
    const float* x      = (const float*)d_in[0];   // (B, 10) float32
    const float* params = (const float*)d_in[1];   // (10,)  float32
    float* out          = (float*)d_out;           // (B, 10) float32

    int B = in_sizes[0] / N_WIRES;                       // 16384
    int warps   = (B + 5) / 6;                           // 2731
    int threads = 512;                                   // 16 warps/block
    int blocks  = (warps * 32 + threads - 1) / threads;  // 171
    qgate_kernel<<<blocks, threads>>>(x, params, out, B);
}